// round 12
// baseline (speedup 1.0000x reference)
#include <cuda_runtime.h>
#include <cuda_fp16.h>

// SpGraphTransAttention on GB300.
// Outputs (flattened tuple): attention [E,4] | v [N,16,4] | prods [E,4]
// Softmax identity: exp(p-max)/sum == exp(p)/sum (p tiny) -> no max pass.
// q and k rows stored fp16 (128B = one L2 line per row); fp32 accumulate.

#define NN_MAX 50000
#define NATT 64
#define TN 48  // nodes per qkv tile

__device__ __half g_qh[NN_MAX * NATT];
__device__ __half g_kh[NN_MAX * NATT];
__device__ float  g_denom[NN_MAX * 4];

// ---- packed f32x2 helpers (FFMA2) ----
__device__ __forceinline__ unsigned long long ffma2(unsigned long long a,
                                                    unsigned long long b,
                                                    unsigned long long c) {
    unsigned long long d;
    asm("fma.rn.f32x2 %0, %1, %2, %3;" : "=l"(d) : "l"(a), "l"(b), "l"(c));
    return d;
}
__device__ __forceinline__ unsigned long long pack2(float lo, float hi) {
    unsigned long long r;
    asm("mov.b64 %0, {%1, %2};" : "=l"(r) : "f"(lo), "f"(hi));
    return r;
}
__device__ __forceinline__ void unpack2(unsigned long long v, float& lo, float& hi) {
    asm("mov.b64 {%0, %1}, %2;" : "=f"(lo), "=f"(hi) : "l"(v));
}

// QKV projection, register-tiled GEMM (4 nodes x 4 cols/thread).
// Grid (ntiles, 3); blockIdx.y = matrix. 192 threads: cq = tid&15, nq = tid>>4.
// minBlocksPerMP=5 caps regs (~68) to lift occupancy above the 4-block RF limit.
__global__ void __launch_bounds__(192, 5) qkv_kernel(
    const float* __restrict__ x,
    const float* __restrict__ Wq, const float* __restrict__ bq,
    const float* __restrict__ Wk, const float* __restrict__ bk,
    const float* __restrict__ Wv, const float* __restrict__ bv,
    float* __restrict__ vout, int n)
{
    __shared__ unsigned long long sW[16][4][16][2];       // 16KB
    __shared__ __align__(16) float sx[TN][64];            // 12KB

    const int tid = threadIdx.x;
    const int m = blockIdx.y;
    const float* __restrict__ W  = (m == 0) ? Wq : (m == 1) ? Wk : Wv;
    const float* __restrict__ bp = (m == 0) ? bq : (m == 1) ? bk : bv;

    // zero g_denom (edge kernel is a later launch); grid.x*192 >= n*4
    if (m == 0) {
        int idx = blockIdx.x * 192 + tid;
        if (idx < n * 4) g_denom[idx] = 0.0f;
    }

    // pack W (row-major [k][j]) into shared, conflict-free layout
    for (int i = tid; i < 16 * 64; i += 192) {
        const int kq = i >> 6, j = i & 63;
        const int cq = j >> 2, jj = j & 3;
        sW[kq][jj][cq][0] = pack2(W[(4 * kq + 0) * 64 + j], W[(4 * kq + 1) * 64 + j]);
        sW[kq][jj][cq][1] = pack2(W[(4 * kq + 2) * 64 + j], W[(4 * kq + 3) * 64 + j]);
    }

    const int cq = tid & 15;
    const int nq = tid >> 4;       // 0..11
    const int j0 = cq * 4;
    const float b0 = bp[j0], b1 = bp[j0 + 1], b2 = bp[j0 + 2], b3 = bp[j0 + 3];

    const int base = blockIdx.x * TN;

    for (int i = tid; i < TN * 16; i += 192) {
        const int node = base + (i >> 4);
        float4 val = (node < n) ? ((const float4*)x)[(size_t)node * 16 + (i & 15)]
                                : make_float4(0.f, 0.f, 0.f, 0.f);
        ((float4*)sx)[i] = val;
    }
    __syncthreads();

    unsigned long long acc[4][4];
#pragma unroll
    for (int l = 0; l < 4; l++)
#pragma unroll
        for (int jj = 0; jj < 4; jj++) acc[l][jj] = 0ULL;

#pragma unroll
    for (int kq = 0; kq < 16; kq++) {
        ulonglong2 xa[4], wv[4];
#pragma unroll
        for (int l = 0; l < 4; l++)
            xa[l] = *(const ulonglong2*)&sx[nq * 4 + l][kq * 4];
#pragma unroll
        for (int jj = 0; jj < 4; jj++)
            wv[jj] = *(const ulonglong2*)&sW[kq][jj][cq][0];
#pragma unroll
        for (int l = 0; l < 4; l++) {
#pragma unroll
            for (int jj = 0; jj < 4; jj++) {
                acc[l][jj] = ffma2(xa[l].x, wv[jj].x, acc[l][jj]);
                acc[l][jj] = ffma2(xa[l].y, wv[jj].y, acc[l][jj]);
            }
        }
    }

#pragma unroll
    for (int l = 0; l < 4; l++) {
        const int node = base + nq * 4 + l;
        if (node >= n) continue;
        float lo, hi;
        unpack2(acc[l][0], lo, hi); const float r0 = lo + hi + b0;
        unpack2(acc[l][1], lo, hi); const float r1 = lo + hi + b1;
        unpack2(acc[l][2], lo, hi); const float r2 = lo + hi + b2;
        unpack2(acc[l][3], lo, hi); const float r3 = lo + hi + b3;
        if (m == 2) {
            // v heads layout [N, d_k, nhead]: col j = h*16+dk -> node*64 + dk*4 + h
            const int h = j0 >> 4;
            const int dk0 = j0 & 15;
            float* vp = vout + (size_t)node * 64 + h;
            vp[(dk0 + 0) * 4] = r0;
            vp[(dk0 + 1) * 4] = r1;
            vp[(dk0 + 2) * 4] = r2;
            vp[(dk0 + 3) * 4] = r3;
        } else {
            // fp16 row store (q or k): 4 halfs = 8B
            const __half2 h2a = __floats2half2_rn(r0, r1);
            const __half2 h2b = __floats2half2_rn(r2, r3);
            uint2 pk;
            pk.x = *(const unsigned int*)&h2a;
            pk.y = *(const unsigned int*)&h2b;
            __half* dst = (m == 0) ? g_qh : g_kh;
            *(uint2*)&dst[(size_t)node * 64 + j0] = pk;
        }
    }
}

// Edge pass, octet-cooperative (8 threads/edge). fp16 rows: 128B each.
// Thread d loads halfs [8d, 8d+8) via ONE LDG.128 per row; each warp
// instruction = 4 edges x one full 128B line -> 2 wavefronts/edge.
// Index loads split by lane parity (src on even, dst on odd) + 2 shfls.
// Head h on lane pair {2h, 2h+1}: one shfl_xor(1) completes the dot.
__global__ void __launch_bounds__(256) edge_kernel(
    const int* __restrict__ e_src, const int* __restrict__ e_dst,
    float4* __restrict__ prods, int E)
{
    const int t = blockIdx.x * 256 + threadIdx.x;
    const int e = t >> 3;
    const int d = t & 7;
    const bool live = (e < E);
    const int ec = live ? e : (E - 1);

    const int lane = threadIdx.x & 31;
    const int obase = lane & ~7;

    // lane-parity index load + distribute
    const int idx = (d & 1) ? e_dst[ec] : e_src[ec];
    const int s  = __shfl_sync(0xFFFFFFFFu, idx, obase + 0);
    const int td = __shfl_sync(0xFFFFFFFFu, idx, obase + 1);

    const uint4* qp = reinterpret_cast<const uint4*>(g_qh + (size_t)s * 64);
    const uint4* kp = reinterpret_cast<const uint4*>(g_kh + (size_t)td * 64);

    const uint4 qv = qp[d];  // halfs [8d, 8d+8)
    const uint4 kv = kp[d];

    const float2 q0 = __half22float2(*(const __half2*)&qv.x);
    const float2 q1 = __half22float2(*(const __half2*)&qv.y);
    const float2 q2 = __half22float2(*(const __half2*)&qv.z);
    const float2 q3 = __half22float2(*(const __half2*)&qv.w);
    const float2 k0 = __half22float2(*(const __half2*)&kv.x);
    const float2 k1 = __half22float2(*(const __half2*)&kv.y);
    const float2 k2 = __half22float2(*(const __half2*)&kv.z);
    const float2 k3 = __half22float2(*(const __half2*)&kv.w);

    float acc = q0.x * k0.x + q0.y * k0.y + q1.x * k1.x + q1.y * k1.y
              + q2.x * k2.x + q2.y * k2.y + q3.x * k3.x + q3.y * k3.y;

    acc += __shfl_xor_sync(0xFFFFFFFFu, acc, 1);  // lanes 2h,2h+1 -> head-h dot

    const float p = acc * 0.25f;  // / sqrt(d_k=16)
    const float ex = __expf(p);

    // gather heads 1..3 (lanes obase+2h) into lane d==0 for the float4 store
    const float p1 = __shfl_sync(0xFFFFFFFFu, p, obase + 2);
    const float p2 = __shfl_sync(0xFFFFFFFFu, p, obase + 4);
    const float p3 = __shfl_sync(0xFFFFFFFFu, p, obase + 6);

    if (live) {
        if (d == 0) prods[e] = make_float4(p, p1, p2, p3);
        if ((d & 1) == 0)  // lanes 0,2,4,6 of octet: one REDG, 4 active/octet
            atomicAdd(&g_denom[s * 4 + (d >> 1)], ex);
    }
}

// Normalize: att[e] = exp(prods[e]) / denom. 4 edges per thread (MLP).
__global__ void __launch_bounds__(256) norm_kernel(
    const int* __restrict__ e_src, const float4* __restrict__ prods,
    float4* __restrict__ att, int E)
{
    const int base = (blockIdx.x * 256 + threadIdx.x) * 4;
#pragma unroll
    for (int u = 0; u < 4; u++) {
        const int e = base + u;
        if (e >= E) return;
        const int s = e_src[e];
        const float4 p = prods[e];
        const float4 dn = *reinterpret_cast<const float4*>(g_denom + s * 4);
        float4 a;
        a.x = __fdividef(__expf(p.x), dn.x + 1e-16f);
        a.y = __fdividef(__expf(p.y), dn.y + 1e-16f);
        a.z = __fdividef(__expf(p.z), dn.z + 1e-16f);
        a.w = __fdividef(__expf(p.w), dn.w + 1e-16f);
        att[e] = a;
    }
}

extern "C" void kernel_launch(void* const* d_in, const int* in_sizes, int n_in,
                              void* d_out, int out_size)
{
    const float* x  = (const float*)d_in[0];
    const int* edge = (const int*)d_in[1];
    const float* Wq = (const float*)d_in[2];
    const float* bq = (const float*)d_in[3];
    const float* Wk = (const float*)d_in[4];
    const float* bk = (const float*)d_in[5];
    const float* Wv = (const float*)d_in[6];
    const float* bv = (const float*)d_in[7];

    const int n = in_sizes[0] / NATT;   // 50000
    const int E = in_sizes[1] / 2;      // 1600000

    float* out   = (float*)d_out;
    float* att   = out;                                   // [E,4]
    float* vout  = out + (size_t)E * 4;                   // [N,16,4]
    float* prods = out + (size_t)E * 4 + (size_t)n * 64;  // [E,4]

    const int ntiles = (n + TN - 1) / TN;                 // 1042: 1042*192 >= n*4
    dim3 qgrid(ntiles, 3);
    qkv_kernel<<<qgrid, 192>>>(x, Wq, bq, Wk, bk, Wv, bv, vout, n);

    const int eblocks = (int)(((long long)E * 8 + 255) / 256);
    edge_kernel<<<eblocks, 256>>>(edge, edge + E, (float4*)prods, E);

    const int nblocks = (E + 1023) / 1024;
    norm_kernel<<<nblocks, 256>>>(edge, (const float4*)prods, (float4*)att, E);
}

// round 13
// speedup vs baseline: 1.0688x; 1.0688x over previous
#include <cuda_runtime.h>
#include <cuda_fp16.h>

// SpGraphTransAttention on GB300.
// Outputs (flattened tuple): attention [E,4] | v [N,16,4] | prods [E,4]
// Softmax identity: exp(p-max)/sum == exp(p)/sum (p tiny) -> no max pass.
// q and k rows stored fp16 (128B = one L2 line per row); fp32 accumulate.
// sx rows padded to 68 floats (272B): the warp's two nq row-groups land on
// different bank groups -> conflict-free broadcast x-loads.

#define NN_MAX 50000
#define NATT 64
#define TN 48   // nodes per qkv tile
#define XP 68   // padded row stride (floats) for sx

__device__ __half g_qh[NN_MAX * NATT];
__device__ __half g_kh[NN_MAX * NATT];
__device__ float  g_denom[NN_MAX * 4];

// ---- packed f32x2 helpers (FFMA2) ----
__device__ __forceinline__ unsigned long long ffma2(unsigned long long a,
                                                    unsigned long long b,
                                                    unsigned long long c) {
    unsigned long long d;
    asm("fma.rn.f32x2 %0, %1, %2, %3;" : "=l"(d) : "l"(a), "l"(b), "l"(c));
    return d;
}
__device__ __forceinline__ unsigned long long pack2(float lo, float hi) {
    unsigned long long r;
    asm("mov.b64 %0, {%1, %2};" : "=l"(r) : "f"(lo), "f"(hi));
    return r;
}
__device__ __forceinline__ void unpack2(unsigned long long v, float& lo, float& hi) {
    asm("mov.b64 {%0, %1}, %2;" : "=f"(lo), "=f"(hi) : "l"(v));
}

// QKV projection, register-tiled GEMM (4 nodes x 4 cols/thread).
// Grid (ntiles, 3); blockIdx.y = matrix. 192 threads: cq = tid&15, nq = tid>>4.
__global__ void __launch_bounds__(192) qkv_kernel(
    const float* __restrict__ x,
    const float* __restrict__ Wq, const float* __restrict__ bq,
    const float* __restrict__ Wk, const float* __restrict__ bk,
    const float* __restrict__ Wv, const float* __restrict__ bv,
    float* __restrict__ vout, int n)
{
    __shared__ unsigned long long sW[16][4][16][2];       // 16KB
    __shared__ __align__(16) float sx[TN][XP];            // 12.75KB padded

    const int tid = threadIdx.x;
    const int m = blockIdx.y;
    const float* __restrict__ W  = (m == 0) ? Wq : (m == 1) ? Wk : Wv;
    const float* __restrict__ bp = (m == 0) ? bq : (m == 1) ? bk : bv;

    // zero g_denom (edge kernel is a later launch); grid.x*192 >= n*4
    if (m == 0) {
        int idx = blockIdx.x * 192 + tid;
        if (idx < n * 4) g_denom[idx] = 0.0f;
    }

    // pack W (row-major [k][j]) into shared, conflict-free layout
    for (int i = tid; i < 16 * 64; i += 192) {
        const int kq = i >> 6, j = i & 63;
        const int cq = j >> 2, jj = j & 3;
        sW[kq][jj][cq][0] = pack2(W[(4 * kq + 0) * 64 + j], W[(4 * kq + 1) * 64 + j]);
        sW[kq][jj][cq][1] = pack2(W[(4 * kq + 2) * 64 + j], W[(4 * kq + 3) * 64 + j]);
    }

    const int cq = tid & 15;
    const int nq = tid >> 4;       // 0..11
    const int j0 = cq * 4;
    const float b0 = bp[j0], b1 = bp[j0 + 1], b2 = bp[j0 + 2], b3 = bp[j0 + 3];

    const int base = blockIdx.x * TN;

    for (int i = tid; i < TN * 16; i += 192) {
        const int row = i >> 4, c4 = i & 15;
        const int node = base + row;
        float4 val = (node < n) ? ((const float4*)x)[(size_t)node * 16 + c4]
                                : make_float4(0.f, 0.f, 0.f, 0.f);
        *(float4*)&sx[row][c4 * 4] = val;
    }
    __syncthreads();

    unsigned long long acc[4][4];
#pragma unroll
    for (int l = 0; l < 4; l++)
#pragma unroll
        for (int jj = 0; jj < 4; jj++) acc[l][jj] = 0ULL;

#pragma unroll
    for (int kq = 0; kq < 16; kq++) {
        ulonglong2 xa[4], wv[4];
#pragma unroll
        for (int l = 0; l < 4; l++)
            xa[l] = *(const ulonglong2*)&sx[nq * 4 + l][kq * 4];
#pragma unroll
        for (int jj = 0; jj < 4; jj++)
            wv[jj] = *(const ulonglong2*)&sW[kq][jj][cq][0];
#pragma unroll
        for (int l = 0; l < 4; l++) {
#pragma unroll
            for (int jj = 0; jj < 4; jj++) {
                acc[l][jj] = ffma2(xa[l].x, wv[jj].x, acc[l][jj]);
                acc[l][jj] = ffma2(xa[l].y, wv[jj].y, acc[l][jj]);
            }
        }
    }

#pragma unroll
    for (int l = 0; l < 4; l++) {
        const int node = base + nq * 4 + l;
        if (node >= n) continue;
        float lo, hi;
        unpack2(acc[l][0], lo, hi); const float r0 = lo + hi + b0;
        unpack2(acc[l][1], lo, hi); const float r1 = lo + hi + b1;
        unpack2(acc[l][2], lo, hi); const float r2 = lo + hi + b2;
        unpack2(acc[l][3], lo, hi); const float r3 = lo + hi + b3;
        if (m == 2) {
            // v heads layout [N, d_k, nhead]: col j = h*16+dk -> node*64 + dk*4 + h
            const int h = j0 >> 4;
            const int dk0 = j0 & 15;
            float* vp = vout + (size_t)node * 64 + h;
            vp[(dk0 + 0) * 4] = r0;
            vp[(dk0 + 1) * 4] = r1;
            vp[(dk0 + 2) * 4] = r2;
            vp[(dk0 + 3) * 4] = r3;
        } else {
            // fp16 row store (q or k): 4 halfs = 8B
            const __half2 h2a = __floats2half2_rn(r0, r1);
            const __half2 h2b = __floats2half2_rn(r2, r3);
            uint2 pk;
            pk.x = *(const unsigned int*)&h2a;
            pk.y = *(const unsigned int*)&h2b;
            __half* dst = (m == 0) ? g_qh : g_kh;
            *(uint2*)&dst[(size_t)node * 64 + j0] = pk;
        }
    }
}

// Edge pass, octet-cooperative (8 threads/edge). fp16 rows: 128B each.
// Thread d loads halfs [8d, 8d+8) via ONE LDG.128 per row (2 loads total);
// each warp instruction = 4 edges x one full 128B line -> 2 wavefronts/edge.
// Head h lives on lane pair {2h, 2h+1}: one shfl_xor(1) completes the dot.
__global__ void __launch_bounds__(256) edge_kernel(
    const int* __restrict__ e_src, const int* __restrict__ e_dst,
    float4* __restrict__ prods, int E)
{
    const int t = blockIdx.x * 256 + threadIdx.x;
    const int e = t >> 3;
    const int d = t & 7;
    const bool live = (e < E);
    const int ec = live ? e : (E - 1);

    const int s  = e_src[ec];
    const int td = e_dst[ec];

    const uint4* qp = reinterpret_cast<const uint4*>(g_qh + (size_t)s * 64);
    const uint4* kp = reinterpret_cast<const uint4*>(g_kh + (size_t)td * 64);

    const uint4 qv = qp[d];  // halfs [8d, 8d+8)
    const uint4 kv = kp[d];

    const float2 q0 = __half22float2(*(const __half2*)&qv.x);
    const float2 q1 = __half22float2(*(const __half2*)&qv.y);
    const float2 q2 = __half22float2(*(const __half2*)&qv.z);
    const float2 q3 = __half22float2(*(const __half2*)&qv.w);
    const float2 k0 = __half22float2(*(const __half2*)&kv.x);
    const float2 k1 = __half22float2(*(const __half2*)&kv.y);
    const float2 k2 = __half22float2(*(const __half2*)&kv.z);
    const float2 k3 = __half22float2(*(const __half2*)&kv.w);

    float acc = q0.x * k0.x + q0.y * k0.y + q1.x * k1.x + q1.y * k1.y
              + q2.x * k2.x + q2.y * k2.y + q3.x * k3.x + q3.y * k3.y;

    acc += __shfl_xor_sync(0xFFFFFFFFu, acc, 1);  // lanes 2h,2h+1 -> head-h dot

    const float p = acc * 0.25f;  // / sqrt(d_k=16)
    const float ex = __expf(p);

    // gather heads 1..3 (lanes obase+2h) into lane d==0 for the float4 store
    const int lane = threadIdx.x & 31;
    const int obase = lane & ~7;
    const float p1 = __shfl_sync(0xFFFFFFFFu, p, obase + 2);
    const float p2 = __shfl_sync(0xFFFFFFFFu, p, obase + 4);
    const float p3 = __shfl_sync(0xFFFFFFFFu, p, obase + 6);

    if (live) {
        if (d == 0) prods[e] = make_float4(p, p1, p2, p3);
        if ((d & 1) == 0)  // lanes 0,2,4,6 of octet: one REDG, 4 active/octet
            atomicAdd(&g_denom[s * 4 + (d >> 1)], ex);
    }
}

// Normalize: att[e] = exp(prods[e]) / denom. 2 edges per thread.
__global__ void __launch_bounds__(256) norm_kernel(
    const int* __restrict__ e_src, const float4* __restrict__ prods,
    float4* __restrict__ att, int E)
{
    const int base = (blockIdx.x * 256 + threadIdx.x) * 2;
#pragma unroll
    for (int u = 0; u < 2; u++) {
        const int e = base + u;
        if (e >= E) return;
        const int s = e_src[e];
        const float4 p = prods[e];
        const float4 dn = *reinterpret_cast<const float4*>(g_denom + s * 4);
        float4 a;
        a.x = __fdividef(__expf(p.x), dn.x + 1e-16f);
        a.y = __fdividef(__expf(p.y), dn.y + 1e-16f);
        a.z = __fdividef(__expf(p.z), dn.z + 1e-16f);
        a.w = __fdividef(__expf(p.w), dn.w + 1e-16f);
        att[e] = a;
    }
}

extern "C" void kernel_launch(void* const* d_in, const int* in_sizes, int n_in,
                              void* d_out, int out_size)
{
    const float* x  = (const float*)d_in[0];
    const int* edge = (const int*)d_in[1];
    const float* Wq = (const float*)d_in[2];
    const float* bq = (const float*)d_in[3];
    const float* Wk = (const float*)d_in[4];
    const float* bk = (const float*)d_in[5];
    const float* Wv = (const float*)d_in[6];
    const float* bv = (const float*)d_in[7];

    const int n = in_sizes[0] / NATT;   // 50000
    const int E = in_sizes[1] / 2;      // 1600000

    float* out   = (float*)d_out;
    float* att   = out;                                   // [E,4]
    float* vout  = out + (size_t)E * 4;                   // [N,16,4]
    float* prods = out + (size_t)E * 4 + (size_t)n * 64;  // [E,4]

    const int ntiles = (n + TN - 1) / TN;                 // 1042: 1042*192 >= n*4
    dim3 qgrid(ntiles, 3);
    qkv_kernel<<<qgrid, 192>>>(x, Wq, bq, Wk, bk, Wv, bv, vout, n);

    const int eblocks = (int)(((long long)E * 8 + 255) / 256);
    edge_kernel<<<eblocks, 256>>>(edge, edge + E, (float4*)prods, E);

    const int nblocks = (E + 511) / 512;
    norm_kernel<<<nblocks, 256>>>(edge, (const float4*)prods, (float4*)att, E);
}